// round 14
// baseline (speedup 1.0000x reference)
#include <cuda_runtime.h>
#include <math.h>

#define SS 1024
#define KK 4
#define NBLK 256        // blocks; 4 rows per block (NBLK*4 == SS)
#define RPB 4

// ---------------- scratch (no allocations allowed) ----------------
__device__ float g_ps[NBLK];               // per-block partial sums
__device__ unsigned int g_done = 0;        // monotonic ticket (never reset)

__device__ __forceinline__ float softplusf(float x) {
    if (x > 20.0f)  return x;
    if (x < -20.0f) return expf(x);
    return log1pf(expf(x));                // accurate: only 3 uniform scalars
}
__device__ __forceinline__ float dot4(float4 a, float4 b) {
    return a.x * b.x + a.y * b.y + a.z * b.z + a.w * b.w;
}
__device__ __forceinline__ float sum4(float4 a) { return a.x + a.y + a.z + a.w; }
__device__ __forceinline__ float4 exp4(float4 v) {
    float4 w; w.x = __expf(v.x); w.y = __expf(v.y); w.z = __expf(v.z); w.w = __expf(v.w);
    return w;
}

__global__ void __launch_bounds__(256, 2) k_fused(
    const float* __restrict__ log_delta,
    const float* __restrict__ log_tau,
    const float* __restrict__ log_lambda,
    const float* __restrict__ E,
    const float* __restrict__ logPi,
    const int*   __restrict__ sC1,
    const int*   __restrict__ sC2,
    const float* __restrict__ recip,
    const int*   __restrict__ splits_c1,
    const int*   __restrict__ splits_c2,
    const float* __restrict__ log_q,
    const void*  __restrict__ is_leaf,
    const int*   __restrict__ rootp,
    float*       __restrict__ out)
{
    __shared__ float s_red[8][64];     // per-warp reduced partials (padded rows)
    __shared__ float s_fin[64];        // block-level sums
    __shared__ float s_part[RPB];
    __shared__ unsigned int s_islast;

    const int tid  = threadIdx.x;      // thread owns float4 slice j4 = tid
    const int b    = blockIdx.x;
    const int warp = tid >> 5, lane = tid & 31;
    const int s0   = b * RPB;

    // ---- uniform scalars ----
    const int root = rootp[0];
    const float delta = softplusf(log_delta[0]);
    const float tau   = softplusf(log_tau[0]);
    const float lam   = softplusf(log_lambda[0]);
    const float rs = 1.0f + delta + tau + lam;
    const float pS = 1.0f / rs, pD = delta / rs, pT = tau / rs, pL = lam / rs;

    const unsigned char* lbp = (const unsigned char*)is_leaf;
    const unsigned int*  lwp = (const unsigned int*)is_leaf;
    const bool leaf = (lbp[root] != 0) || (lwp[root] == 0x3F800000u);

    int c[8];
    #pragma unroll
    for (int k = 0; k < KK; k++) {
        c[k]     = splits_c1[root * KK + k];
        c[4 + k] = splits_c2[root * KK + k];
    }
    int i1[RPB], i2[RPB];
    #pragma unroll
    for (int r = 0; r < RPB; r++) { i1[r] = sC1[s0 + r]; i2[r] = sC2[s0 + r]; }

    // ---- weight rows in REGISTERS (this thread's slice only; no smem staging) ----
    float4 wv[8];
    #pragma unroll
    for (int k = 0; k < 8; k++)
        wv[k] = exp4(((const float4*)(logPi + (size_t)c[k] * SS))[tid]);
    const float4 ev = ((const float4*)E)[tid];

    // ---- 56 dot partials over this thread's slice ----
    float acc[40 + 4 * RPB];

    float4 rcur = ((const float4*)(recip + (size_t)s0 * SS))[tid];
    #pragma unroll
    for (int r = 0; r < RPB; r++) {
        float4 rnext = rcur;
        if (r + 1 < RPB) rnext = ((const float4*)(recip + (size_t)(s0 + r + 1) * SS))[tid];
        acc[r * 10 + 0] = sum4(rcur);
        acc[r * 10 + 1] = dot4(rcur, ev);
        #pragma unroll
        for (int k = 0; k < 8; k++)
            acc[r * 10 + 2 + k] = dot4(rcur, wv[k]);
        rcur = rnext;
    }
    // aux rows i1, i2 per row: cnt + E-dot (for local E_new recomputation)
    #pragma unroll
    for (int r = 0; r < RPB; r++) {
        float4 a1 = ((const float4*)(recip + (size_t)i1[r] * SS))[tid];
        float4 a2 = ((const float4*)(recip + (size_t)i2[r] * SS))[tid];
        acc[40 + r * 4 + 0] = sum4(a1);
        acc[40 + r * 4 + 1] = dot4(a1, ev);
        acc[40 + r * 4 + 2] = sum4(a2);
        acc[40 + r * 4 + 3] = dot4(a2, ev);
    }

    // ---- warp reduce all 56, then cross-warp via smem ----
    #pragma unroll
    for (int q = 0; q < 56; q++)
        #pragma unroll
        for (int o = 16; o > 0; o >>= 1)
            acc[q] += __shfl_xor_sync(0xffffffffu, acc[q], o);
    if (lane == 0)
        #pragma unroll
        for (int q = 0; q < 56; q++) s_red[warp][q] = acc[q];
    __syncthreads();
    if (tid < 56) {
        float t = 0.0f;
        #pragma unroll
        for (int w2 = 0; w2 < 8; w2++) t += s_red[w2][tid];
        s_fin[tid] = t;
    }
    __syncthreads();

    // ---- epilogue: warp r handles row s0+r; point values gathered from logPi ----
    if (warp < RPB) {
        const int r = warp;
        const int s = s0 + r;
        float lin = 0.0f;
        if (leaf) {
            if (lane == 0) lin = __expf(logPi[(size_t)root * SS + s]);
        } else {
            const int I1 = i1[r], I2 = i2[r];
            if (lane < 4) {
                const int k = lane;
                const float q = __expf(log_q[root * KK + k]);
                const float* rA = logPi + (size_t)c[k] * SS;
                const float* rB = logPi + (size_t)c[4 + k] * SS;
                float A  = __expf(rA[s]),  B  = __expf(rB[s]);
                float Af = __expf(rA[I1]), Ag = __expf(rA[I2]);
                float Bf = __expf(rB[I1]), Bg = __expf(rB[I2]);
                float inv = 1.0f / fmaxf(s_fin[r * 10 + 0], 1.0f);
                float sA = s_fin[r * 10 + 2 + k];
                float sB = s_fin[r * 10 + 6 + k];
                lin = q * (pS * (Af * Bg + Ag * Bf)
                         + pD * (A * B)
                         + pT * inv * (A * sB + B * sA));
            }
            lin += __shfl_xor_sync(0xffffffffu, lin, 1);
            lin += __shfl_xor_sync(0xffffffffu, lin, 2);   // k-sum on lane 0
            if (lane == 0) {
                float inv1 = 1.0f / fmaxf(s_fin[40 + r * 4 + 0], 1.0f);
                float inv2 = 1.0f / fmaxf(s_fin[40 + r * 4 + 2], 1.0f);
                float E1 = E[I1], E2 = E[I2];
                float En1 = pL + pD * E1 * E1 + pT * E1 * (s_fin[40 + r * 4 + 1] * inv1)
                          + pS * E[sC1[I1]] * E[sC2[I1]];
                float En2 = pL + pD * E2 * E2 + pT * E2 * (s_fin[40 + r * 4 + 3] * inv2)
                          + pS * E[sC1[I2]] * E[sC2[I2]];
                float P1 = __expf(logPi[(size_t)root * SS + I1]);
                float P2 = __expf(logPi[(size_t)root * SS + I2]);
                lin += pS * (P1 * En2 + P2 * En1);
            }
        }
        if (lane == 0) s_part[r] = lin;
    }
    __syncthreads();

    // ---- per-block sum + ticket ----
    if (tid == 0) {
        g_ps[b] = s_part[0] + s_part[1] + s_part[2] + s_part[3];
        __threadfence();                   // release partial
        unsigned int prev = atomicAdd(&g_done, 1u);
        s_islast = ((prev % NBLK) == (unsigned int)(NBLK - 1)) ? 1u : 0u;
    }
    __syncthreads();
    if (!s_islast) return;
    __threadfence();                       // acquire: all partials visible

    // ---- last block: fixed-order deterministic final sum + one log ----
    if (warp == 0) {
        float v = 0.0f;
        #pragma unroll
        for (int m = 0; m < NBLK / 32; m++) v += g_ps[lane + m * 32];
        #pragma unroll
        for (int o = 16; o > 0; o >>= 1)
            v += __shfl_xor_sync(0xffffffffu, v, o);
        if (lane == 0) out[0] = logf(v);
    }
}

// ---------------- launch ----------------
extern "C" void kernel_launch(void* const* d_in, const int* in_sizes, int n_in,
                              void* d_out, int out_size)
{
    const float* log_delta  = (const float*)d_in[0];
    const float* log_tau    = (const float*)d_in[1];
    const float* log_lambda = (const float*)d_in[2];
    const float* E          = (const float*)d_in[3];
    const float* log_Pi     = (const float*)d_in[4];
    const int*   s_C1       = (const int*)  d_in[5];
    const int*   s_C2       = (const int*)  d_in[6];
    const float* recip      = (const float*)d_in[7];
    const int*   splits_c1  = (const int*)  d_in[8];
    const int*   splits_c2  = (const int*)  d_in[9];
    const float* log_q      = (const float*)d_in[10];
    const void*  is_leaf    = (const void*) d_in[11];
    const int*   root_id    = (const int*)  d_in[12];
    float* out = (float*)d_out;

    k_fused<<<NBLK, 256>>>(log_delta, log_tau, log_lambda, E, log_Pi,
                           s_C1, s_C2, recip, splits_c1, splits_c2,
                           log_q, is_leaf, root_id, out);
}

// round 15
// speedup vs baseline: 1.0025x; 1.0025x over previous
#include <cuda_runtime.h>
#include <math.h>

#define SS 1024
#define KK 4
#define NBLK 256        // blocks; 4 rows per block (NBLK*4 == SS); 2/SM -> one wave
#define RPB 4

// ---------------- scratch (no allocations allowed) ----------------
__device__ float g_ps[NBLK];               // per-block partial sums
__device__ unsigned int g_done = 0;        // monotonic ticket (never reset)

__device__ __forceinline__ float softplusf(float x) {
    if (x > 20.0f)  return x;
    if (x < -20.0f) return expf(x);
    return log1pf(expf(x));                // accurate: only 3 uniform scalars
}
__device__ __forceinline__ float dot4(float4 a, float4 b) {
    return a.x * b.x + a.y * b.y + a.z * b.z + a.w * b.w;
}
__device__ __forceinline__ float sum4(float4 a) { return a.x + a.y + a.z + a.w; }
__device__ __forceinline__ float4 exp4(float4 v) {
    float4 w; w.x = __expf(v.x); w.y = __expf(v.y); w.z = __expf(v.z); w.w = __expf(v.w);
    return w;
}

__global__ void __launch_bounds__(256, 2) k_fused(
    const float* __restrict__ log_delta,
    const float* __restrict__ log_tau,
    const float* __restrict__ log_lambda,
    const float* __restrict__ E,
    const float* __restrict__ logPi,
    const int*   __restrict__ sC1,
    const int*   __restrict__ sC2,
    const float* __restrict__ recip,
    const int*   __restrict__ splits_c1,
    const int*   __restrict__ splits_c2,
    const float* __restrict__ log_q,
    const void*  __restrict__ is_leaf,
    const int*   __restrict__ rootp,
    float*       __restrict__ out)
{
    __shared__ float s_red[8][48];     // per-warp reduced partials (40 used, padded)
    __shared__ float s_fin[48];        // block-level sums
    __shared__ float s_part[RPB];
    __shared__ unsigned int s_islast;

    const int tid  = threadIdx.x;      // thread owns float4 slice j4 = tid
    const int b    = blockIdx.x;
    const int warp = tid >> 5, lane = tid & 31;
    const int s0   = b * RPB;

    // ---- uniform scalars ----
    const int root = rootp[0];
    const float delta = softplusf(log_delta[0]);
    const float tau   = softplusf(log_tau[0]);
    const float lam   = softplusf(log_lambda[0]);
    const float rs = 1.0f + delta + tau + lam;
    const float pS = 1.0f / rs, pD = delta / rs, pT = tau / rs, pL = lam / rs;

    const unsigned char* lbp = (const unsigned char*)is_leaf;
    const unsigned int*  lwp = (const unsigned int*)is_leaf;
    const bool leaf = (lbp[root] != 0) || (lwp[root] == 0x3F800000u);

    int c[8];
    #pragma unroll
    for (int k = 0; k < KK; k++) {
        c[k]     = splits_c1[root * KK + k];
        c[4 + k] = splits_c2[root * KK + k];
    }
    // per-row index chains (issued early; independent of everything below)
    int i1[RPB], i2[RPB];
    #pragma unroll
    for (int r = 0; r < RPB; r++) { i1[r] = sC1[s0 + r]; i2[r] = sC2[s0 + r]; }

    // ---- weight rows in REGISTERS (this thread's slice only) ----
    float4 wv[8];
    #pragma unroll
    for (int k = 0; k < 8; k++)
        wv[k] = exp4(((const float4*)(logPi + (size_t)c[k] * SS))[tid]);
    const float4 ev = ((const float4*)E)[tid];

    // ---- 40 dot partials over this thread's slice (4 rows x 10) ----
    float acc[10 * RPB];
    #pragma unroll
    for (int r = 0; r < RPB; r++) {
        const float4 rcur = ((const float4*)(recip + (size_t)(s0 + r) * SS))[tid];
        acc[r * 10 + 0] = sum4(rcur);
        acc[r * 10 + 1] = dot4(rcur, ev);
        #pragma unroll
        for (int k = 0; k < 8; k++)
            acc[r * 10 + 2 + k] = dot4(rcur, wv[k]);
    }

    // ---- warp reduce all 40, then cross-warp via smem ----
    #pragma unroll
    for (int q = 0; q < 40; q++)
        #pragma unroll
        for (int o = 16; o > 0; o >>= 1)
            acc[q] += __shfl_xor_sync(0xffffffffu, acc[q], o);
    if (lane == 0)
        #pragma unroll
        for (int q = 0; q < 40; q++) s_red[warp][q] = acc[q];
    __syncthreads();
    if (tid < 40) {
        float t = 0.0f;
        #pragma unroll
        for (int w2 = 0; w2 < 8; w2++) t += s_red[w2][tid];
        s_fin[tid] = t;
    }
    __syncthreads();

    // ---- epilogue: warp r handles row s0+r (aux dots done here, off main reg budget) ----
    if (warp < RPB) {
        const int r = warp;
        const int s = s0 + r;
        float lin = 0.0f;
        if (leaf) {
            if (lane == 0) lin = __expf(logPi[(size_t)root * SS + s]);
        } else {
            const int I1 = i1[r], I2 = i2[r];

            // aux dots: cnt + E-dot for rows I1, I2 (8 float4 per lane, L2-resident)
            float a0 = 0.0f, a1 = 0.0f, a2 = 0.0f, a3 = 0.0f;
            const float4* r1 = (const float4*)(recip + (size_t)I1 * SS);
            const float4* r2 = (const float4*)(recip + (size_t)I2 * SS);
            #pragma unroll
            for (int it = 0; it < 8; it++) {
                const int j4 = lane + it * 32;
                const float4 x1 = r1[j4];
                const float4 x2 = r2[j4];
                const float4 e4 = ((const float4*)E)[j4];
                a0 += sum4(x1); a1 += dot4(x1, e4);
                a2 += sum4(x2); a3 += dot4(x2, e4);
            }
            #pragma unroll
            for (int o = 16; o > 0; o >>= 1) {
                a0 += __shfl_xor_sync(0xffffffffu, a0, o);
                a1 += __shfl_xor_sync(0xffffffffu, a1, o);
                a2 += __shfl_xor_sync(0xffffffffu, a2, o);
                a3 += __shfl_xor_sync(0xffffffffu, a3, o);
            }

            if (lane < 4) {
                const int k = lane;
                const float q = __expf(log_q[root * KK + k]);
                const float* rA = logPi + (size_t)c[k] * SS;
                const float* rB = logPi + (size_t)c[4 + k] * SS;
                float A  = __expf(rA[s]),  B  = __expf(rB[s]);
                float Af = __expf(rA[I1]), Ag = __expf(rA[I2]);
                float Bf = __expf(rB[I1]), Bg = __expf(rB[I2]);
                float inv = 1.0f / fmaxf(s_fin[r * 10 + 0], 1.0f);
                float sA = s_fin[r * 10 + 2 + k];
                float sB = s_fin[r * 10 + 6 + k];
                lin = q * (pS * (Af * Bg + Ag * Bf)
                         + pD * (A * B)
                         + pT * inv * (A * sB + B * sA));
            }
            lin += __shfl_xor_sync(0xffffffffu, lin, 1);
            lin += __shfl_xor_sync(0xffffffffu, lin, 2);   // k-sum on lane 0
            if (lane == 0) {
                float inv1 = 1.0f / fmaxf(a0, 1.0f);
                float inv2 = 1.0f / fmaxf(a2, 1.0f);
                float E1 = E[I1], E2 = E[I2];
                float En1 = pL + pD * E1 * E1 + pT * E1 * (a1 * inv1)
                          + pS * E[sC1[I1]] * E[sC2[I1]];
                float En2 = pL + pD * E2 * E2 + pT * E2 * (a3 * inv2)
                          + pS * E[sC1[I2]] * E[sC2[I2]];
                float P1 = __expf(logPi[(size_t)root * SS + I1]);
                float P2 = __expf(logPi[(size_t)root * SS + I2]);
                lin += pS * (P1 * En2 + P2 * En1);
            }
        }
        if (lane == 0) s_part[r] = lin;
    }
    __syncthreads();

    // ---- per-block sum + ticket ----
    if (tid == 0) {
        g_ps[b] = s_part[0] + s_part[1] + s_part[2] + s_part[3];
        __threadfence();                   // release partial
        unsigned int prev = atomicAdd(&g_done, 1u);
        s_islast = ((prev % NBLK) == (unsigned int)(NBLK - 1)) ? 1u : 0u;
    }
    __syncthreads();
    if (!s_islast) return;
    __threadfence();                       // acquire: all partials visible

    // ---- last block: fixed-order deterministic final sum + one log ----
    if (warp == 0) {
        float v = 0.0f;
        #pragma unroll
        for (int m = 0; m < NBLK / 32; m++) v += g_ps[lane + m * 32];
        #pragma unroll
        for (int o = 16; o > 0; o >>= 1)
            v += __shfl_xor_sync(0xffffffffu, v, o);
        if (lane == 0) out[0] = logf(v);
    }
}

// ---------------- launch ----------------
extern "C" void kernel_launch(void* const* d_in, const int* in_sizes, int n_in,
                              void* d_out, int out_size)
{
    const float* log_delta  = (const float*)d_in[0];
    const float* log_tau    = (const float*)d_in[1];
    const float* log_lambda = (const float*)d_in[2];
    const float* E          = (const float*)d_in[3];
    const float* log_Pi     = (const float*)d_in[4];
    const int*   s_C1       = (const int*)  d_in[5];
    const int*   s_C2       = (const int*)  d_in[6];
    const float* recip      = (const float*)d_in[7];
    const int*   splits_c1  = (const int*)  d_in[8];
    const int*   splits_c2  = (const int*)  d_in[9];
    const float* log_q      = (const float*)d_in[10];
    const void*  is_leaf    = (const void*) d_in[11];
    const int*   root_id    = (const int*)  d_in[12];
    float* out = (float*)d_out;

    k_fused<<<NBLK, 256>>>(log_delta, log_tau, log_lambda, E, log_Pi,
                           s_C1, s_C2, recip, splits_c1, splits_c2,
                           log_q, is_leaf, root_id, out);
}